// round 1
// baseline (speedup 1.0000x reference)
#include <cuda_runtime.h>
#include <cuda_bf16.h>

// ---------------- problem constants ----------------
#define B_SZ     2
#define L_SEQ    1024
#define D_MODEL  1024
#define D_INNER  4096
#define N_STATE  16
#define DT_RANK  64
#define D_CONV   4
#define M_ROWS   (B_SZ * L_SEQ)          // 2048
#define XDBL_N   (DT_RANK + 2 * N_STATE) // 96

// ---------------- scratch (device globals; no allocs allowed) ----------------
__device__ float g_xz   [(long)M_ROWS * 2 * D_INNER]; // 2048 x 8192  (xc | res)
__device__ float g_u    [(long)M_ROWS * D_INNER];     // 2048 x 4096
__device__ float g_xdbl [(long)M_ROWS * XDBL_N];      // 2048 x 96
__device__ float g_delta[(long)M_ROWS * D_INNER];     // 2048 x 4096
__device__ float g_y    [(long)M_ROWS * D_INNER];     // 2048 x 4096

// ---------------- helpers ----------------
__device__ __forceinline__ float siluf(float x) {
    return x / (1.0f + __expf(-x));
}
__device__ __forceinline__ float softplusf(float x) {
    // matches jax.nn.softplus = max(x,0) + log1p(exp(-|x|))
    return (x > 0.0f) ? (x + log1pf(expf(-x))) : log1pf(expf(x));
}

// ---------------- big-tile SGEMM: 128x128x8, 256 thr, 8x8 microtile ----------
// Requires: M % 128 == 0 (via grid), N % 128 == 0 (via grid), K % 8 == 0,
// lda/ldb/ldc multiples of 4. EPI: 0 = none, 1 = softplus.
template<int EPI>
__global__ __launch_bounds__(256)
void sgemm128(const float* __restrict__ A, int lda,
              const float* __restrict__ B, int ldb,
              float* __restrict__ C, int ldc, int K)
{
    constexpr int BK = 8;
    __shared__ float As[BK][128];
    __shared__ float Bs[BK][128];

    const int tid = threadIdx.x;
    const int bm  = blockIdx.y * 128;
    const int bn  = blockIdx.x * 128;

    const int tm = (tid >> 4) * 8;   // 0..120
    const int tn = (tid & 15) * 8;   // 0..120

    const int arow = tid >> 1;        // 0..127
    const int acol = (tid & 1) * 4;   // 0 or 4
    const int brow = tid >> 5;        // 0..7
    const int bcol = (tid & 31) * 4;  // 0..124

    const float* Aptr = A + (long)(bm + arow) * lda + acol;
    const float* Bptr = B + (long)brow * ldb + bn + bcol;

    float acc[8][8];
#pragma unroll
    for (int i = 0; i < 8; i++)
#pragma unroll
        for (int j = 0; j < 8; j++) acc[i][j] = 0.0f;

    for (int k0 = 0; k0 < K; k0 += BK) {
        float4 av = *reinterpret_cast<const float4*>(Aptr);
        float4 bv = *reinterpret_cast<const float4*>(Bptr);
        As[acol + 0][arow] = av.x;
        As[acol + 1][arow] = av.y;
        As[acol + 2][arow] = av.z;
        As[acol + 3][arow] = av.w;
        *reinterpret_cast<float4*>(&Bs[brow][bcol]) = bv;
        __syncthreads();

#pragma unroll
        for (int k = 0; k < BK; k++) {
            float4 a0 = *reinterpret_cast<const float4*>(&As[k][tm]);
            float4 a1 = *reinterpret_cast<const float4*>(&As[k][tm + 4]);
            float4 b0 = *reinterpret_cast<const float4*>(&Bs[k][tn]);
            float4 b1 = *reinterpret_cast<const float4*>(&Bs[k][tn + 4]);
            float a[8] = {a0.x, a0.y, a0.z, a0.w, a1.x, a1.y, a1.z, a1.w};
            float b[8] = {b0.x, b0.y, b0.z, b0.w, b1.x, b1.y, b1.z, b1.w};
#pragma unroll
            for (int i = 0; i < 8; i++)
#pragma unroll
                for (int j = 0; j < 8; j++)
                    acc[i][j] = fmaf(a[i], b[j], acc[i][j]);
        }
        __syncthreads();
        Aptr += BK;
        Bptr += (long)BK * ldb;
    }

#pragma unroll
    for (int i = 0; i < 8; i++) {
        float* crow = C + (long)(bm + tm + i) * ldc + bn + tn;
        float v[8];
#pragma unroll
        for (int j = 0; j < 8; j++) {
            float t = acc[i][j];
            if (EPI == 1) t = softplusf(t);
            v[j] = t;
        }
        *reinterpret_cast<float4*>(crow)     = make_float4(v[0], v[1], v[2], v[3]);
        *reinterpret_cast<float4*>(crow + 4) = make_float4(v[4], v[5], v[6], v[7]);
    }
}

// ---------------- small SGEMM for N=96 (x_dbl = u @ Wx) --------------------
// BM=32, BN=96, BK=32, TM=TN=4, 192 threads. Exact-fit for M=2048,N=96,K=4096.
__global__ __launch_bounds__(192)
void sgemm_small(const float* __restrict__ A, int lda,
                 const float* __restrict__ B, int ldb,
                 float* __restrict__ C, int ldc, int K)
{
    constexpr int BM = 32, BN = 96, BK = 32;
    __shared__ float As[BK][BM];
    __shared__ float Bs[BK][BN];

    const int tid = threadIdx.x;
    const int bm  = blockIdx.y * BM;
    const int tm  = (tid / 24) * 4;  // 0..28
    const int tn  = (tid % 24) * 4;  // 0..92

    float acc[4][4];
#pragma unroll
    for (int i = 0; i < 4; i++)
#pragma unroll
        for (int j = 0; j < 4; j++) acc[i][j] = 0.0f;

    for (int k0 = 0; k0 < K; k0 += BK) {
        for (int i = tid; i < BM * BK; i += 192) {
            int m = i >> 5, k = i & 31;
            As[k][m] = A[(long)(bm + m) * lda + k0 + k];
        }
        for (int i = tid; i < BK * BN; i += 192) {
            int k = i / BN, n = i % BN;
            Bs[k][n] = B[(long)(k0 + k) * ldb + n];
        }
        __syncthreads();
#pragma unroll
        for (int k = 0; k < BK; k++) {
            float a[4], b[4];
#pragma unroll
            for (int i = 0; i < 4; i++) a[i] = As[k][tm + i];
#pragma unroll
            for (int j = 0; j < 4; j++) b[j] = Bs[k][tn + j];
#pragma unroll
            for (int i = 0; i < 4; i++)
#pragma unroll
                for (int j = 0; j < 4; j++)
                    acc[i][j] = fmaf(a[i], b[j], acc[i][j]);
        }
        __syncthreads();
    }

#pragma unroll
    for (int i = 0; i < 4; i++)
#pragma unroll
        for (int j = 0; j < 4; j++)
            C[(long)(bm + tm + i) * ldc + tn + j] = acc[i][j];
}

// ---------------- depthwise causal conv(4) + bias + SiLU -------------------
__global__ __launch_bounds__(256)
void conv_silu_kernel(const float* __restrict__ Wconv,
                      const float* __restrict__ bconv)
{
    int idx = blockIdx.x * 256 + threadIdx.x;          // over B*L*D_INNER
    int d = idx & (D_INNER - 1);
    int t = (idx >> 12) & (L_SEQ - 1);
    int b = idx >> 22;

    float w0 = Wconv[d * 4 + 0];
    float w1 = Wconv[d * 4 + 1];
    float w2 = Wconv[d * 4 + 2];
    float w3 = Wconv[d * 4 + 3];

    long rowbase = (long)(b * L_SEQ) * (2 * D_INNER);
    float acc = bconv[d];
    if (t - 3 >= 0) acc = fmaf(g_xz[rowbase + (long)(t - 3) * (2 * D_INNER) + d], w0, acc);
    if (t - 2 >= 0) acc = fmaf(g_xz[rowbase + (long)(t - 2) * (2 * D_INNER) + d], w1, acc);
    if (t - 1 >= 0) acc = fmaf(g_xz[rowbase + (long)(t - 1) * (2 * D_INNER) + d], w2, acc);
    acc = fmaf(g_xz[rowbase + (long)t * (2 * D_INNER) + d], w3, acc);

    g_u[(long)(b * L_SEQ + t) * D_INNER + d] = siluf(acc);
}

// ---------------- selective scan + epilogue --------------------------------
// 64 blocks x 128 threads: one thread per (b, d) channel; h[16] in registers.
// Fast path: A[n] == (n+1)*A[0] (true for this problem's A_log) -> 1 exp/t.
__global__ __launch_bounds__(128)
void scan_kernel(const float* __restrict__ A_log,
                 const float* __restrict__ Dp)
{
    const int b = blockIdx.x >> 5;                  // 0..1
    const int d = ((blockIdx.x & 31) << 7) + threadIdx.x; // 0..4095

    __shared__ float sBC[2][2 * N_STATE];

    float A[N_STATE];
#pragma unroll
    for (int n = 0; n < N_STATE; n++)
        A[n] = -__expf(A_log[d * N_STATE + n]);
    const float A1 = A[0];
    bool fast = true;
#pragma unroll
    for (int n = 1; n < N_STATE; n++)
        fast = fast && (fabsf(A[n] - (float)(n + 1) * A1) <= 1e-4f * fabsf(A[n]) + 1e-30f);

    const float Dd = Dp[d];
    float h[N_STATE];
#pragma unroll
    for (int n = 0; n < N_STATE; n++) h[n] = 0.0f;

    const long base = (long)b * L_SEQ;
    if (threadIdx.x < 2 * N_STATE)
        sBC[0][threadIdx.x] = g_xdbl[base * XDBL_N + DT_RANK + threadIdx.x];
    __syncthreads();

    for (int t = 0; t < L_SEQ; t++) {
        const long row = base + t;
        if (t + 1 < L_SEQ && threadIdx.x < 2 * N_STATE)
            sBC[(t + 1) & 1][threadIdx.x] =
                g_xdbl[(row + 1) * XDBL_N + DT_RANK + threadIdx.x];

        const float dt = g_delta[row * D_INNER + d];
        const float uu = g_u[row * D_INNER + d];
        const float rr = g_xz[row * (2 * D_INNER) + D_INNER + d];
        const float* BC = sBC[t & 1];
        const float dtu = dt * uu;

        float yv = 0.0f;
        if (fast) {
            const float p = __expf(dt * A1);
            float da = p;
#pragma unroll
            for (int n = 0; n < N_STATE; n++) {
                h[n] = fmaf(da, h[n], dtu * BC[n]);
                yv = fmaf(h[n], BC[N_STATE + n], yv);
                da *= p;
            }
        } else {
#pragma unroll
            for (int n = 0; n < N_STATE; n++) {
                float da = __expf(dt * A[n]);
                h[n] = fmaf(da, h[n], dtu * BC[n]);
                yv = fmaf(h[n], BC[N_STATE + n], yv);
            }
        }

        g_y[row * D_INNER + d] = (yv + uu * Dd) * siluf(rr);
        __syncthreads();
    }
}

// ---------------- launcher ----------------
extern "C" void kernel_launch(void* const* d_in, const int* in_sizes, int n_in,
                              void* d_out, int out_size)
{
    (void)in_sizes; (void)n_in; (void)out_size;
    const float* x     = (const float*)d_in[0];
    const float* Win   = (const float*)d_in[1];
    const float* Wconv = (const float*)d_in[2];
    const float* bconv = (const float*)d_in[3];
    const float* Wx    = (const float*)d_in[4];
    const float* Wdt   = (const float*)d_in[5];
    const float* A_log = (const float*)d_in[6];
    const float* D     = (const float*)d_in[7];
    const float* Wout  = (const float*)d_in[8];
    float* out = (float*)d_out;

    float *xz, *u, *xdbl, *delta, *y;
    cudaGetSymbolAddress((void**)&xz,    g_xz);
    cudaGetSymbolAddress((void**)&u,     g_u);
    cudaGetSymbolAddress((void**)&xdbl,  g_xdbl);
    cudaGetSymbolAddress((void**)&delta, g_delta);
    cudaGetSymbolAddress((void**)&y,     g_y);

    // 1. xz = x @ Win                      (2048 x 8192 x 1024)
    sgemm128<0><<<dim3(2 * D_INNER / 128, M_ROWS / 128), 256>>>(
        x, D_MODEL, Win, 2 * D_INNER, xz, 2 * D_INNER, D_MODEL);

    // 2. u = silu(depthwise_conv(xc) + bconv)
    conv_silu_kernel<<<(B_SZ * L_SEQ * D_INNER) / 256, 256>>>(Wconv, bconv);

    // 3. x_dbl = u @ Wx                    (2048 x 96 x 4096)
    sgemm_small<<<dim3(1, M_ROWS / 32), 192>>>(
        u, D_INNER, Wx, XDBL_N, xdbl, XDBL_N, D_INNER);

    // 4. delta = softplus(x_dbl[:, :64] @ Wdt)   (2048 x 4096 x 64)
    sgemm128<1><<<dim3(D_INNER / 128, M_ROWS / 128), 256>>>(
        xdbl, XDBL_N, Wdt, D_INNER, delta, D_INNER, DT_RANK);

    // 5. selective scan + (y + u*D) * silu(res)
    scan_kernel<<<64, 128>>>(A_log, D);

    // 6. out = y @ Wout                    (2048 x 1024 x 4096)
    sgemm128<0><<<dim3(D_MODEL / 128, M_ROWS / 128), 256>>>(
        y, D_INNER, Wout, D_MODEL, out, D_MODEL, D_INNER);
}

// round 2
// speedup vs baseline: 1.3282x; 1.3282x over previous
#include <cuda_runtime.h>
#include <cuda_bf16.h>

// ---------------- problem constants ----------------
#define B_SZ     2
#define L_SEQ    1024
#define D_MODEL  1024
#define D_INNER  4096
#define N_STATE  16
#define DT_RANK  64
#define D_CONV   4
#define M_ROWS   (B_SZ * L_SEQ)          // 2048
#define XDBL_N   (DT_RANK + 2 * N_STATE) // 96

// ---------------- scratch (device globals; no allocs allowed) ----------------
__device__ float g_xz   [(long)M_ROWS * 2 * D_INNER]; // 2048 x 8192  (xc | res)
__device__ float g_u    [(long)M_ROWS * D_INNER];     // 2048 x 4096
__device__ float g_xdbl [(long)M_ROWS * XDBL_N];      // 2048 x 96
__device__ float g_delta[(long)M_ROWS * D_INNER];     // 2048 x 4096
__device__ float g_y    [(long)M_ROWS * D_INNER];     // 2048 x 4096

// ---------------- helpers ----------------
__device__ __forceinline__ float siluf(float x) {
    return x / (1.0f + __expf(-x));
}
__device__ __forceinline__ float softplusf(float x) {
    // matches jax.nn.softplus = max(x,0) + log1p(exp(-|x|))
    return (x > 0.0f) ? (x + log1pf(expf(-x))) : log1pf(expf(x));
}

// packed fp32x2 FMA: d = a * b + d (lanewise on a 64-bit register pair).
// Bit-identical to two fmaf's; 2x issue-slot efficiency vs 3-reg FFMA.
__device__ __forceinline__ void ffma2(unsigned long long& d,
                                      unsigned long long a,
                                      unsigned long long b) {
    asm("fma.rn.f32x2 %0, %1, %2, %0;" : "+l"(d) : "l"(a), "l"(b));
}
__device__ __forceinline__ unsigned long long bcast2(float x) {
    unsigned long long r;
    asm("mov.b64 %0, {%1, %1};" : "=l"(r) : "f"(x));
    return r;
}
__device__ __forceinline__ void unpack2(float& lo, float& hi, unsigned long long v) {
    asm("mov.b64 {%0, %1}, %2;" : "=f"(lo), "=f"(hi) : "l"(v));
}

// ---------------- big-tile SGEMM: 128x128x8, 256 thr, 8x8 microtile ----------
// Packed f32x2 FMAs + double-buffered smem + global prefetch.
// Requires: M,N multiples of 128 (via grid), K % 8 == 0, leading dims mult of 4.
// EPI: 0 = none, 1 = softplus.
template<int EPI>
__global__ __launch_bounds__(256)
void sgemm128(const float* __restrict__ A, int lda,
              const float* __restrict__ B, int ldb,
              float* __restrict__ C, int ldc, int K)
{
    constexpr int BK = 8;
    __shared__ __align__(16) float As[2][BK][128];
    __shared__ __align__(16) float Bs[2][BK][128];

    const int tid = threadIdx.x;
    const int bm  = blockIdx.y * 128;
    const int bn  = blockIdx.x * 128;

    const int tm = (tid >> 4) * 8;   // 0..120 (row offset of 8-row microtile)
    const int tn = (tid & 15) * 8;   // 0..120 (col offset)

    const int arow = tid >> 1;        // 0..127
    const int acol = (tid & 1) * 4;   // 0 or 4
    const int brow = tid >> 5;        // 0..7
    const int bcol = (tid & 31) * 4;  // 0..124

    const float* Aptr = A + (long)(bm + arow) * lda + acol;
    const float* Bptr = B + (long)brow * ldb + bn + bcol;

    // 4 row-pairs x 8 cols of packed accumulators (== 8x8 floats)
    unsigned long long acc[4][8];
#pragma unroll
    for (int i = 0; i < 4; i++)
#pragma unroll
        for (int j = 0; j < 8; j++) acc[i][j] = 0ull;

    const int T = K / BK;

    // preload tile 0
    float4 av = *reinterpret_cast<const float4*>(Aptr);
    float4 bv = *reinterpret_cast<const float4*>(Bptr);
    As[0][acol + 0][arow] = av.x;
    As[0][acol + 1][arow] = av.y;
    As[0][acol + 2][arow] = av.z;
    As[0][acol + 3][arow] = av.w;
    *reinterpret_cast<float4*>(&Bs[0][brow][bcol]) = bv;
    __syncthreads();

    int buf = 0;
    for (int t = 0; t < T; t++) {
        if (t + 1 < T) {
            Aptr += BK;
            Bptr += (long)BK * ldb;
            av = *reinterpret_cast<const float4*>(Aptr);
            bv = *reinterpret_cast<const float4*>(Bptr);
        }

#pragma unroll
        for (int k = 0; k < BK; k++) {
            // A row-pairs: 8 floats = 4 packed f32x2, straight from shared
            ulonglong2 a01 = *reinterpret_cast<const ulonglong2*>(&As[buf][k][tm]);
            ulonglong2 a23 = *reinterpret_cast<const ulonglong2*>(&As[buf][k][tm + 4]);
            unsigned long long ap[4] = {a01.x, a01.y, a23.x, a23.y};
            // B cols: load 8, broadcast-pack each
            float4 b0 = *reinterpret_cast<const float4*>(&Bs[buf][k][tn]);
            float4 b1 = *reinterpret_cast<const float4*>(&Bs[buf][k][tn + 4]);
            float bf[8] = {b0.x, b0.y, b0.z, b0.w, b1.x, b1.y, b1.z, b1.w};
            unsigned long long bb[8];
#pragma unroll
            for (int j = 0; j < 8; j++) bb[j] = bcast2(bf[j]);
#pragma unroll
            for (int i = 0; i < 4; i++)
#pragma unroll
                for (int j = 0; j < 8; j++)
                    ffma2(acc[i][j], ap[i], bb[j]);
        }

        if (t + 1 < T) {
            int nb = buf ^ 1;
            As[nb][acol + 0][arow] = av.x;
            As[nb][acol + 1][arow] = av.y;
            As[nb][acol + 2][arow] = av.z;
            As[nb][acol + 3][arow] = av.w;
            *reinterpret_cast<float4*>(&Bs[nb][brow][bcol]) = bv;
            __syncthreads();
            buf = nb;
        }
    }

    // epilogue: unpack row-pairs and store
#pragma unroll
    for (int i = 0; i < 4; i++) {
        float lo[8], hi[8];
#pragma unroll
        for (int j = 0; j < 8; j++) {
            unpack2(lo[j], hi[j], acc[i][j]);
            if (EPI == 1) { lo[j] = softplusf(lo[j]); hi[j] = softplusf(hi[j]); }
        }
        float* c0 = C + (long)(bm + tm + 2 * i) * ldc + bn + tn;
        float* c1 = c0 + ldc;
        *reinterpret_cast<float4*>(c0)     = make_float4(lo[0], lo[1], lo[2], lo[3]);
        *reinterpret_cast<float4*>(c0 + 4) = make_float4(lo[4], lo[5], lo[6], lo[7]);
        *reinterpret_cast<float4*>(c1)     = make_float4(hi[0], hi[1], hi[2], hi[3]);
        *reinterpret_cast<float4*>(c1 + 4) = make_float4(hi[4], hi[5], hi[6], hi[7]);
    }
}

// ---------------- small SGEMM for N=96 (x_dbl = u @ Wx) --------------------
// BM=32, BN=96, BK=32, TM=TN=4, 192 threads.
__global__ __launch_bounds__(192)
void sgemm_small(const float* __restrict__ A, int lda,
                 const float* __restrict__ B, int ldb,
                 float* __restrict__ C, int ldc, int K)
{
    constexpr int BM = 32, BN = 96, BK = 32;
    __shared__ float As[BK][BM];
    __shared__ float Bs[BK][BN];

    const int tid = threadIdx.x;
    const int bm  = blockIdx.y * BM;
    const int tm  = (tid / 24) * 4;  // 0..28
    const int tn  = (tid % 24) * 4;  // 0..92

    float acc[4][4];
#pragma unroll
    for (int i = 0; i < 4; i++)
#pragma unroll
        for (int j = 0; j < 4; j++) acc[i][j] = 0.0f;

    for (int k0 = 0; k0 < K; k0 += BK) {
        for (int i = tid; i < BM * BK; i += 192) {
            int m = i >> 5, k = i & 31;
            As[k][m] = A[(long)(bm + m) * lda + k0 + k];
        }
        for (int i = tid; i < BK * BN; i += 192) {
            int k = i / BN, n = i % BN;
            Bs[k][n] = B[(long)(k0 + k) * ldb + n];
        }
        __syncthreads();
#pragma unroll
        for (int k = 0; k < BK; k++) {
            float a[4], b[4];
#pragma unroll
            for (int i = 0; i < 4; i++) a[i] = As[k][tm + i];
#pragma unroll
            for (int j = 0; j < 4; j++) b[j] = Bs[k][tn + j];
#pragma unroll
            for (int i = 0; i < 4; i++)
#pragma unroll
                for (int j = 0; j < 4; j++)
                    acc[i][j] = fmaf(a[i], b[j], acc[i][j]);
        }
        __syncthreads();
    }

#pragma unroll
    for (int i = 0; i < 4; i++)
#pragma unroll
        for (int j = 0; j < 4; j++)
            C[(long)(bm + tm + i) * ldc + tn + j] = acc[i][j];
}

// ---------------- depthwise causal conv(4) + bias + SiLU -------------------
__global__ __launch_bounds__(256)
void conv_silu_kernel(const float* __restrict__ Wconv,
                      const float* __restrict__ bconv)
{
    int idx = blockIdx.x * 256 + threadIdx.x;          // over B*L*D_INNER
    int d = idx & (D_INNER - 1);
    int t = (idx >> 12) & (L_SEQ - 1);
    int b = idx >> 22;

    float w0 = Wconv[d * 4 + 0];
    float w1 = Wconv[d * 4 + 1];
    float w2 = Wconv[d * 4 + 2];
    float w3 = Wconv[d * 4 + 3];

    long rowbase = (long)(b * L_SEQ) * (2 * D_INNER);
    float acc = bconv[d];
    if (t - 3 >= 0) acc = fmaf(g_xz[rowbase + (long)(t - 3) * (2 * D_INNER) + d], w0, acc);
    if (t - 2 >= 0) acc = fmaf(g_xz[rowbase + (long)(t - 2) * (2 * D_INNER) + d], w1, acc);
    if (t - 1 >= 0) acc = fmaf(g_xz[rowbase + (long)(t - 1) * (2 * D_INNER) + d], w2, acc);
    acc = fmaf(g_xz[rowbase + (long)t * (2 * D_INNER) + d], w3, acc);

    g_u[(long)(b * L_SEQ + t) * D_INNER + d] = siluf(acc);
}

// ---------------- selective scan + epilogue --------------------------------
// 64 blocks x 128 threads: one thread per (b, d) channel; h[16] in registers.
// All B/C rows for this batch staged once into 128KB dynamic smem (no per-t
// barrier); delta/u/res software-pipelined 4 deep.
// Fast path: A[n] == (n+1)*A[0] (true for this problem's A_log) -> 1 exp/t.
__global__ __launch_bounds__(128)
void scan_kernel(const float* __restrict__ A_log,
                 const float* __restrict__ Dp)
{
    extern __shared__ __align__(16) float sBC[];   // [L_SEQ][32]
    const int b = blockIdx.x >> 5;                         // 0..1
    const int d = ((blockIdx.x & 31) << 7) + threadIdx.x;  // 0..4095
    const long base = (long)b * L_SEQ;

    // stage all B,C rows for this batch (vectorized, coalesced)
    for (int i = threadIdx.x * 4; i < L_SEQ * 32; i += 128 * 4) {
        int t = i >> 5, c = i & 31;
        *reinterpret_cast<float4*>(&sBC[i]) =
            *reinterpret_cast<const float4*>(&g_xdbl[(base + t) * XDBL_N + DT_RANK + c]);
    }
    __syncthreads();

    float A[N_STATE];
#pragma unroll
    for (int n = 0; n < N_STATE; n++)
        A[n] = -__expf(A_log[d * N_STATE + n]);
    const float A1 = A[0];
    bool fast = true;
#pragma unroll
    for (int n = 1; n < N_STATE; n++)
        fast = fast && (fabsf(A[n] - (float)(n + 1) * A1) <= 1e-4f * fabsf(A[n]) + 1e-30f);

    const float Dd = Dp[d];
    float h[N_STATE];
#pragma unroll
    for (int n = 0; n < N_STATE; n++) h[n] = 0.0f;

    // prefetch pipeline (depth 4)
    float pdt[4], pu[4], pr[4];
#pragma unroll
    for (int q = 0; q < 4; q++) {
        long row = base + q;
        pdt[q] = g_delta[row * D_INNER + d];
        pu[q]  = g_u[row * D_INNER + d];
        pr[q]  = g_xz[row * (2 * D_INNER) + D_INNER + d];
    }

    for (int t0 = 0; t0 < L_SEQ; t0 += 4) {
        float cdt[4], cu[4], cr[4];
#pragma unroll
        for (int q = 0; q < 4; q++) { cdt[q] = pdt[q]; cu[q] = pu[q]; cr[q] = pr[q]; }

        if (t0 + 4 < L_SEQ) {
#pragma unroll
            for (int q = 0; q < 4; q++) {
                long row = base + t0 + 4 + q;
                pdt[q] = g_delta[row * D_INNER + d];
                pu[q]  = g_u[row * D_INNER + d];
                pr[q]  = g_xz[row * (2 * D_INNER) + D_INNER + d];
            }
        }

#pragma unroll
        for (int q = 0; q < 4; q++) {
            const int t = t0 + q;
            const float* BC = &sBC[t * 32];
            const float dt = cdt[q], uu = cu[q], rr = cr[q];
            const float dtu = dt * uu;
            float yv = 0.0f;
            if (fast) {
                const float p = __expf(dt * A1);
                float da = p;
#pragma unroll
                for (int n = 0; n < N_STATE; n++) {
                    h[n] = fmaf(da, h[n], dtu * BC[n]);
                    yv = fmaf(h[n], BC[N_STATE + n], yv);
                    da *= p;
                }
            } else {
#pragma unroll
                for (int n = 0; n < N_STATE; n++) {
                    float da = __expf(dt * A[n]);
                    h[n] = fmaf(da, h[n], dtu * BC[n]);
                    yv = fmaf(h[n], BC[N_STATE + n], yv);
                }
            }
            g_y[(base + t) * D_INNER + d] = (yv + uu * Dd) * siluf(rr);
        }
    }
}

// ---------------- launcher ----------------
extern "C" void kernel_launch(void* const* d_in, const int* in_sizes, int n_in,
                              void* d_out, int out_size)
{
    (void)in_sizes; (void)n_in; (void)out_size;
    const float* x     = (const float*)d_in[0];
    const float* Win   = (const float*)d_in[1];
    const float* Wconv = (const float*)d_in[2];
    const float* bconv = (const float*)d_in[3];
    const float* Wx    = (const float*)d_in[4];
    const float* Wdt   = (const float*)d_in[5];
    const float* A_log = (const float*)d_in[6];
    const float* D     = (const float*)d_in[7];
    const float* Wout  = (const float*)d_in[8];
    float* out = (float*)d_out;

    float *xz, *u, *xdbl, *delta, *y;
    cudaGetSymbolAddress((void**)&xz,    g_xz);
    cudaGetSymbolAddress((void**)&u,     g_u);
    cudaGetSymbolAddress((void**)&xdbl,  g_xdbl);
    cudaGetSymbolAddress((void**)&delta, g_delta);
    cudaGetSymbolAddress((void**)&y,     g_y);

    const int scan_smem = L_SEQ * 32 * sizeof(float);   // 128KB
    cudaFuncSetAttribute(scan_kernel,
                         cudaFuncAttributeMaxDynamicSharedMemorySize, scan_smem);

    // 1. xz = x @ Win                      (2048 x 8192 x 1024)
    sgemm128<0><<<dim3(2 * D_INNER / 128, M_ROWS / 128), 256>>>(
        x, D_MODEL, Win, 2 * D_INNER, xz, 2 * D_INNER, D_MODEL);

    // 2. u = silu(depthwise_conv(xc) + bconv)
    conv_silu_kernel<<<(B_SZ * L_SEQ * D_INNER) / 256, 256>>>(Wconv, bconv);

    // 3. x_dbl = u @ Wx                    (2048 x 96 x 4096)
    sgemm_small<<<dim3(1, M_ROWS / 32), 192>>>(
        u, D_INNER, Wx, XDBL_N, xdbl, XDBL_N, D_INNER);

    // 4. delta = softplus(x_dbl[:, :64] @ Wdt)   (2048 x 4096 x 64)
    sgemm128<1><<<dim3(D_INNER / 128, M_ROWS / 128), 256>>>(
        xdbl, XDBL_N, Wdt, D_INNER, delta, D_INNER, DT_RANK);

    // 5. selective scan + (y + u*D) * silu(res)
    scan_kernel<<<64, 128, scan_smem>>>(A_log, D);

    // 6. out = y @ Wout                    (2048 x 1024 x 4096)
    sgemm128<0><<<dim3(D_MODEL / 128, M_ROWS / 128), 256>>>(
        y, D_INNER, Wout, D_MODEL, out, D_MODEL, D_INNER);
}

// round 4
// speedup vs baseline: 1.8865x; 1.4204x over previous
#include <cuda_runtime.h>
#include <cuda_bf16.h>

// ---------------- problem constants ----------------
#define B_SZ     2
#define L_SEQ    1024
#define D_MODEL  1024
#define D_INNER  4096
#define N_STATE  16
#define DT_RANK  64
#define M_ROWS   (B_SZ * L_SEQ)          // 2048
#define XDBL_N   (DT_RANK + 2 * N_STATE) // 96

// ---------------- scratch (device globals; no allocs allowed) ----------------
__device__ float g_xz   [(long)M_ROWS * 2 * D_INNER]; // 2048 x 8192  (xc | res)
__device__ float g_u    [(long)M_ROWS * D_INNER];     // 2048 x 4096
__device__ float g_xdbl [(long)M_ROWS * XDBL_N];      // 2048 x 96
__device__ float g_delta[(long)M_ROWS * D_INNER];     // 2048 x 4096
__device__ float g_y    [(long)M_ROWS * D_INNER];     // 2048 x 4096
// split activation A' = [Ah | Al | Ah]  (max: 2048 x 12288)
__device__ __nv_bfloat16 g_ap[(long)M_ROWS * 3 * D_INNER];
// split+transposed weights W' = [Wh | Wh | Wl]  (max: 8192 x 3072)
__device__ __nv_bfloat16 g_wp[(long)(2 * D_INNER) * 3 * D_MODEL];

// ---------------- helpers ----------------
__device__ __forceinline__ float siluf(float x) { return x / (1.0f + __expf(-x)); }
__device__ __forceinline__ float softplusf(float x) {
    return (x > 0.0f) ? (x + log1pf(expf(-x))) : log1pf(expf(x));
}
__device__ __forceinline__ unsigned smem_u32(const void* p) {
    unsigned a;
    asm("{ .reg .u64 t; cvta.to.shared.u64 t, %1; cvt.u32.u64 %0, t; }" : "=r"(a) : "l"(p));
    return a;
}
#define SWZ128(o) ((o) ^ (((o) >> 3) & 0x70))

__device__ __forceinline__ void ldsm4(unsigned* r, unsigned addr) {
    asm volatile("ldmatrix.sync.aligned.m8n8.x4.shared.b16 {%0,%1,%2,%3}, [%4];"
                 : "=r"(r[0]), "=r"(r[1]), "=r"(r[2]), "=r"(r[3]) : "r"(addr));
}
__device__ __forceinline__ void mma16816(float* c, const unsigned* a, const unsigned* b) {
    asm volatile("mma.sync.aligned.m16n8k16.row.col.f32.bf16.bf16.f32 "
                 "{%0,%1,%2,%3}, {%4,%5,%6,%7}, {%8,%9}, {%0,%1,%2,%3};"
                 : "+f"(c[0]), "+f"(c[1]), "+f"(c[2]), "+f"(c[3])
                 : "r"(a[0]), "r"(a[1]), "r"(a[2]), "r"(a[3]), "r"(b[0]), "r"(b[1]));
}

// ---------------- split prep kernels ----------------
// A'[m, 0:K]=Ah, A'[m, K:2K]=Al, A'[m, 2K:3K]=Ah
__global__ __launch_bounds__(256)
void prep_act(const float* __restrict__ A, int lda, int K,
              __nv_bfloat16* __restrict__ Ap)
{
    long idx = (long)blockIdx.x * 256 + threadIdx.x;
    long m = idx / K;
    int  k = (int)(idx % K);
    float a = A[m * lda + k];
    __nv_bfloat16 hb = __float2bfloat16(a);
    float h = __bfloat162float(hb);
    __nv_bfloat16 lb = __float2bfloat16(a - h);
    long o = m * (3L * K);
    Ap[o + k]         = hb;
    Ap[o + K + k]     = lb;
    Ap[o + 2 * K + k] = hb;
}

// W[K,N] -> W'[N,3K]: seg0=Wh, seg1=Wh, seg2=Wl (transposed via smem tile)
__global__ __launch_bounds__(256)
void prep_w(const float* __restrict__ W, int N, int K,
            __nv_bfloat16* __restrict__ Wp)
{
    __shared__ float th[32][33];
    __shared__ float tl[32][33];
    int bk = blockIdx.x * 32, bn = blockIdx.y * 32;
    int tx = threadIdx.x & 31, ty = threadIdx.x >> 5;  // (32, 8)
#pragma unroll
    for (int j = 0; j < 4; j++) {
        int k = bk + ty + j * 8;
        float w = W[(long)k * N + bn + tx];
        float h = __bfloat162float(__float2bfloat16(w));
        th[ty + j * 8][tx] = h;
        tl[ty + j * 8][tx] = w - h;
    }
    __syncthreads();
#pragma unroll
    for (int j = 0; j < 4; j++) {
        int n = bn + ty + j * 8;
        long o = (long)n * (3L * K);
        __nv_bfloat16 hb = __float2bfloat16(th[tx][ty + j * 8]);
        __nv_bfloat16 lb = __float2bfloat16(tl[tx][ty + j * 8]);
        Wp[o + bk + tx]         = hb;
        Wp[o + K + bk + tx]     = hb;
        Wp[o + 2 * K + bk + tx] = lb;
    }
}

// ---------------- warp-MMA bf16 GEMM: C[M,N] = A'[M,K'] @ W'[N,K']^T -------
// 128x128 CTA tile, BK=64 bf16 (128B rows, SW128), double-buffered smem,
// 8 warps each computing a 32x64 warp tile with mma.sync.m16n8k16.
// EPI: 0 = none, 1 = softplus.
#define GSMEM_TOTAL 65536
#define OFF_A0 0u
#define OFF_A1 16384u
#define OFF_B0 32768u
#define OFF_B1 49152u

template<int EPI>
__global__ __launch_bounds__(256)
void gemm_mma(const __nv_bfloat16* __restrict__ Ap, int lda,
              const __nv_bfloat16* __restrict__ Bp, int ldb,
              float* __restrict__ C, int ldc, int T)
{
    extern __shared__ __align__(1024) char smem[];
    const unsigned sb = smem_u32(smem);
    const int tid  = threadIdx.x;
    const int lane = tid & 31;
    const int wid  = tid >> 5;
    const int wm   = (wid & 3) * 32;   // warp row offset in CTA tile
    const int wn   = (wid >> 2) * 64;  // warp col offset
    const long bm  = (long)blockIdx.y * 128;
    const long bn  = (long)blockIdx.x * 128;

    const int ldr = tid >> 3;              // 0..31: used with +32*i -> rows 0..127
    const int ldc8 = (tid & 7) * 8;        // element col (8 bf16 = 16B chunks)

    float acc[2][8][4];
#pragma unroll
    for (int i = 0; i < 2; i++)
#pragma unroll
        for (int j = 0; j < 8; j++)
#pragma unroll
            for (int r = 0; r < 4; r++) acc[i][j][r] = 0.0f;

    uint4 ra[4], rb[4];
    // ---- preload tile 0 into regs ----
    {
        const __nv_bfloat16* Ab = Ap + bm * lda;
        const __nv_bfloat16* Bb = Bp + bn * ldb;
#pragma unroll
        for (int i = 0; i < 4; i++) {
            int r = ldr + 32 * i;
            ra[i] = *reinterpret_cast<const uint4*>(Ab + (long)r * lda + ldc8);
            rb[i] = *reinterpret_cast<const uint4*>(Bb + (long)r * ldb + ldc8);
        }
    }
    // ---- store tile 0 to smem buf 0 (swizzled) ----
#pragma unroll
    for (int i = 0; i < 4; i++) {
        int r = ldr + 32 * i;
        unsigned sw = SWZ128((unsigned)(r * 128 + ldc8 * 2));
        *reinterpret_cast<uint4*>(smem + OFF_A0 + sw) = ra[i];
        *reinterpret_cast<uint4*>(smem + OFF_B0 + sw) = rb[i];
    }
    __syncthreads();

    for (int t = 0; t < T; t++) {
        const int p = t & 1;
        // prefetch tile t+1 from global
        if (t + 1 < T) {
            const __nv_bfloat16* Ab = Ap + bm * lda + (long)(t + 1) * 64;
            const __nv_bfloat16* Bb = Bp + bn * ldb + (long)(t + 1) * 64;
#pragma unroll
            for (int i = 0; i < 4; i++) {
                int r = ldr + 32 * i;
                ra[i] = *reinterpret_cast<const uint4*>(Ab + (long)r * lda + ldc8);
                rb[i] = *reinterpret_cast<const uint4*>(Bb + (long)r * ldb + ldc8);
            }
        }

        // ---- compute on buffer p ----
        const unsigned sA = sb + (p ? OFF_A1 : OFF_A0);
        const unsigned sB = sb + (p ? OFF_B1 : OFF_B0);
        const int lr = lane & 15;        // row within 16-row ldmatrix tile
        const int lh = (lane >> 4) * 16; // 0 or 16 bytes (k half)
#pragma unroll
        for (int ks = 0; ks < 4; ks++) {
            const int kb = ks * 32;  // byte offset of this k16 step
            unsigned af[2][4];
#pragma unroll
            for (int im = 0; im < 2; im++) {
                unsigned addr = sA + SWZ128((unsigned)((wm + im * 16 + lr) * 128 + kb + lh));
                ldsm4(af[im], addr);
            }
            unsigned bf[8][2];
#pragma unroll
            for (int jn = 0; jn < 4; jn++) {
                unsigned q[4];
                unsigned addr = sB + SWZ128((unsigned)((wn + jn * 16 + lr) * 128 + kb + lh));
                ldsm4(q, addr);
                bf[2 * jn][0]     = q[0];
                bf[2 * jn][1]     = q[2];
                bf[2 * jn + 1][0] = q[1];
                bf[2 * jn + 1][1] = q[3];
            }
#pragma unroll
            for (int im = 0; im < 2; im++)
#pragma unroll
                for (int j = 0; j < 8; j++)
                    mma16816(acc[im][j], af[im], bf[j]);
        }

        // ---- store prefetched tile into other buffer ----
        if (t + 1 < T) {
            const unsigned dA = (p ? OFF_A0 : OFF_A1);
            const unsigned dB = (p ? OFF_B0 : OFF_B1);
#pragma unroll
            for (int i = 0; i < 4; i++) {
                int r = ldr + 32 * i;
                unsigned sw = SWZ128((unsigned)(r * 128 + ldc8 * 2));
                *reinterpret_cast<uint4*>(smem + dA + sw) = ra[i];
                *reinterpret_cast<uint4*>(smem + dB + sw) = rb[i];
            }
        }
        __syncthreads();
    }

    // ---- epilogue ----
    const int gid = lane >> 2;        // 0..7
    const int tig = lane & 3;         // 0..3
#pragma unroll
    for (int im = 0; im < 2; im++) {
        long m0 = bm + wm + im * 16 + gid;
#pragma unroll
        for (int j = 0; j < 8; j++) {
            long n0 = bn + wn + j * 8 + 2 * tig;
            float c0 = acc[im][j][0], c1 = acc[im][j][1];
            float c2 = acc[im][j][2], c3 = acc[im][j][3];
            if (EPI == 1) {
                c0 = softplusf(c0); c1 = softplusf(c1);
                c2 = softplusf(c2); c3 = softplusf(c3);
            }
            *reinterpret_cast<float2*>(C + m0 * ldc + n0)       = make_float2(c0, c1);
            *reinterpret_cast<float2*>(C + (m0 + 8) * ldc + n0) = make_float2(c2, c3);
        }
    }
}

// ---------------- small SGEMM for N=96 (x_dbl = u @ Wx) --------------------
__global__ __launch_bounds__(192)
void sgemm_small(const float* __restrict__ A, int lda,
                 const float* __restrict__ B, int ldb,
                 float* __restrict__ C, int ldc, int K)
{
    constexpr int BM = 32, BN = 96, BK = 32;
    __shared__ float As[BK][BM];
    __shared__ float Bs[BK][BN];
    const int tid = threadIdx.x;
    const int bm  = blockIdx.y * BM;
    const int tm  = (tid / 24) * 4;
    const int tn  = (tid % 24) * 4;

    float acc[4][4];
#pragma unroll
    for (int i = 0; i < 4; i++)
#pragma unroll
        for (int j = 0; j < 4; j++) acc[i][j] = 0.0f;

    for (int k0 = 0; k0 < K; k0 += BK) {
        for (int i = tid; i < BM * BK; i += 192) {
            int m = i >> 5, k = i & 31;
            As[k][m] = A[(long)(bm + m) * lda + k0 + k];
        }
        for (int i = tid; i < BK * BN; i += 192) {
            int k = i / BN, n = i % BN;
            Bs[k][n] = B[(long)(k0 + k) * ldb + n];
        }
        __syncthreads();
#pragma unroll
        for (int k = 0; k < BK; k++) {
            float a[4], b[4];
#pragma unroll
            for (int i = 0; i < 4; i++) a[i] = As[k][tm + i];
#pragma unroll
            for (int j = 0; j < 4; j++) b[j] = Bs[k][tn + j];
#pragma unroll
            for (int i = 0; i < 4; i++)
#pragma unroll
                for (int j = 0; j < 4; j++)
                    acc[i][j] = fmaf(a[i], b[j], acc[i][j]);
        }
        __syncthreads();
    }
#pragma unroll
    for (int i = 0; i < 4; i++)
#pragma unroll
        for (int j = 0; j < 4; j++)
            C[(long)(bm + tm + i) * ldc + tn + j] = acc[i][j];
}

// ---------------- depthwise causal conv(4) + bias + SiLU -------------------
__global__ __launch_bounds__(256)
void conv_silu_kernel(const float* __restrict__ Wconv,
                      const float* __restrict__ bconv)
{
    int idx = blockIdx.x * 256 + threadIdx.x;
    int d = idx & (D_INNER - 1);
    int t = (idx >> 12) & (L_SEQ - 1);
    int b = idx >> 22;

    float w0 = Wconv[d * 4 + 0], w1 = Wconv[d * 4 + 1];
    float w2 = Wconv[d * 4 + 2], w3 = Wconv[d * 4 + 3];

    long rowbase = (long)(b * L_SEQ) * (2 * D_INNER);
    float acc = bconv[d];
    if (t - 3 >= 0) acc = fmaf(g_xz[rowbase + (long)(t - 3) * (2 * D_INNER) + d], w0, acc);
    if (t - 2 >= 0) acc = fmaf(g_xz[rowbase + (long)(t - 2) * (2 * D_INNER) + d], w1, acc);
    if (t - 1 >= 0) acc = fmaf(g_xz[rowbase + (long)(t - 1) * (2 * D_INNER) + d], w2, acc);
    acc = fmaf(g_xz[rowbase + (long)t * (2 * D_INNER) + d], w3, acc);

    g_u[(long)(b * L_SEQ + t) * D_INNER + d] = siluf(acc);
}

// ---------------- selective scan + epilogue --------------------------------
__global__ __launch_bounds__(128)
void scan_kernel(const float* __restrict__ A_log,
                 const float* __restrict__ Dp)
{
    extern __shared__ __align__(16) float sBC[];   // [L_SEQ][32]
    const int b = blockIdx.x >> 5;
    const int d = ((blockIdx.x & 31) << 7) + threadIdx.x;
    const long base = (long)b * L_SEQ;

    for (int i = threadIdx.x * 4; i < L_SEQ * 32; i += 128 * 4) {
        int t = i >> 5, c = i & 31;
        *reinterpret_cast<float4*>(&sBC[i]) =
            *reinterpret_cast<const float4*>(&g_xdbl[(base + t) * XDBL_N + DT_RANK + c]);
    }
    __syncthreads();

    float A[N_STATE];
#pragma unroll
    for (int n = 0; n < N_STATE; n++)
        A[n] = -__expf(A_log[d * N_STATE + n]);
    const float A1 = A[0];
    bool fast = true;
#pragma unroll
    for (int n = 1; n < N_STATE; n++)
        fast = fast && (fabsf(A[n] - (float)(n + 1) * A1) <= 1e-4f * fabsf(A[n]) + 1e-30f);

    const float Dd = Dp[d];
    float h[N_STATE];
#pragma unroll
    for (int n = 0; n < N_STATE; n++) h[n] = 0.0f;

    float pdt[4], pu[4], pr[4];
#pragma unroll
    for (int q = 0; q < 4; q++) {
        long row = base + q;
        pdt[q] = g_delta[row * D_INNER + d];
        pu[q]  = g_u[row * D_INNER + d];
        pr[q]  = g_xz[row * (2 * D_INNER) + D_INNER + d];
    }

    for (int t0 = 0; t0 < L_SEQ; t0 += 4) {
        float cdt[4], cu[4], cr[4];
#pragma unroll
        for (int q = 0; q < 4; q++) { cdt[q] = pdt[q]; cu[q] = pu[q]; cr[q] = pr[q]; }
        if (t0 + 4 < L_SEQ) {
#pragma unroll
            for (int q = 0; q < 4; q++) {
                long row = base + t0 + 4 + q;
                pdt[q] = g_delta[row * D_INNER + d];
                pu[q]  = g_u[row * D_INNER + d];
                pr[q]  = g_xz[row * (2 * D_INNER) + D_INNER + d];
            }
        }
#pragma unroll
        for (int q = 0; q < 4; q++) {
            const int t = t0 + q;
            const float* BC = &sBC[t * 32];
            const float dt = cdt[q], uu = cu[q], rr = cr[q];
            const float dtu = dt * uu;
            float yv = 0.0f;
            if (fast) {
                const float p = __expf(dt * A1);
                float da = p;
#pragma unroll
                for (int n = 0; n < N_STATE; n++) {
                    h[n] = fmaf(da, h[n], dtu * BC[n]);
                    yv = fmaf(h[n], BC[N_STATE + n], yv);
                    da *= p;
                }
            } else {
#pragma unroll
                for (int n = 0; n < N_STATE; n++) {
                    float da = __expf(dt * A[n]);
                    h[n] = fmaf(da, h[n], dtu * BC[n]);
                    yv = fmaf(h[n], BC[N_STATE + n], yv);
                }
            }
            g_y[(base + t) * D_INNER + d] = (yv + uu * Dd) * siluf(rr);
        }
    }
}

// ---------------- launcher ----------------
extern "C" void kernel_launch(void* const* d_in, const int* in_sizes, int n_in,
                              void* d_out, int out_size)
{
    (void)in_sizes; (void)n_in; (void)out_size;
    const float* x     = (const float*)d_in[0];
    const float* Win   = (const float*)d_in[1];
    const float* Wconv = (const float*)d_in[2];
    const float* bconv = (const float*)d_in[3];
    const float* Wx    = (const float*)d_in[4];
    const float* Wdt   = (const float*)d_in[5];
    const float* A_log = (const float*)d_in[6];
    const float* D     = (const float*)d_in[7];
    const float* Wout  = (const float*)d_in[8];
    float* out = (float*)d_out;

    float *xz, *u, *xdbl, *delta, *y;
    __nv_bfloat16 *ap, *wp;
    cudaGetSymbolAddress((void**)&xz,    g_xz);
    cudaGetSymbolAddress((void**)&u,     g_u);
    cudaGetSymbolAddress((void**)&xdbl,  g_xdbl);
    cudaGetSymbolAddress((void**)&delta, g_delta);
    cudaGetSymbolAddress((void**)&y,     g_y);
    cudaGetSymbolAddress((void**)&ap,    g_ap);
    cudaGetSymbolAddress((void**)&wp,    g_wp);

    cudaFuncSetAttribute(gemm_mma<0>, cudaFuncAttributeMaxDynamicSharedMemorySize, GSMEM_TOTAL);
    cudaFuncSetAttribute(gemm_mma<1>, cudaFuncAttributeMaxDynamicSharedMemorySize, GSMEM_TOTAL);
    const int scan_smem = L_SEQ * 32 * sizeof(float);
    cudaFuncSetAttribute(scan_kernel, cudaFuncAttributeMaxDynamicSharedMemorySize, scan_smem);

    // ---- GEMM1: xz = x @ Win   (2048 x 8192 x 1024) ----
    prep_w<<<dim3(D_MODEL / 32, 2 * D_INNER / 32), 256>>>(Win, 2 * D_INNER, D_MODEL, wp);
    prep_act<<<(M_ROWS * D_MODEL) / 256, 256>>>(x, D_MODEL, D_MODEL, ap);
    gemm_mma<0><<<dim3(2 * D_INNER / 128, M_ROWS / 128), 256, GSMEM_TOTAL>>>(
        ap, 3 * D_MODEL, wp, 3 * D_MODEL, xz, 2 * D_INNER, 3 * D_MODEL / 64);

    // ---- conv + SiLU -> u ----
    conv_silu_kernel<<<(B_SZ * L_SEQ * D_INNER) / 256, 256>>>(Wconv, bconv);

    // ---- x_dbl = u @ Wx   (2048 x 96 x 4096) ----
    sgemm_small<<<dim3(1, M_ROWS / 32), 192>>>(u, D_INNER, Wx, XDBL_N, xdbl, XDBL_N, D_INNER);

    // ---- delta = softplus(x_dbl[:, :64] @ Wdt)  (2048 x 4096 x 64) ----
    prep_w<<<dim3(DT_RANK / 32, D_INNER / 32), 256>>>(Wdt, D_INNER, DT_RANK, wp);
    prep_act<<<(M_ROWS * DT_RANK) / 256, 256>>>(xdbl, XDBL_N, DT_RANK, ap);
    gemm_mma<1><<<dim3(D_INNER / 128, M_ROWS / 128), 256, GSMEM_TOTAL>>>(
        ap, 3 * DT_RANK, wp, 3 * DT_RANK, delta, D_INNER, 3 * DT_RANK / 64);

    // ---- selective scan + epilogue ----
    scan_kernel<<<64, 128, scan_smem>>>(A_log, D);

    // ---- out = y @ Wout   (2048 x 1024 x 4096) ----
    prep_w<<<dim3(D_INNER / 32, D_MODEL / 32), 256>>>(Wout, D_MODEL, D_INNER, wp);
    prep_act<<<(M_ROWS * D_INNER) / 256, 256>>>(y, D_INNER, D_INNER, ap);
    gemm_mma<0><<<dim3(D_MODEL / 128, M_ROWS / 128), 256, GSMEM_TOTAL>>>(
        ap, 3 * D_INNER, wp, 3 * D_INNER, out, D_MODEL, 3 * D_INNER / 64);
}

// round 5
// speedup vs baseline: 2.6476x; 1.4034x over previous
#include <cuda_runtime.h>
#include <cuda_bf16.h>

// ---------------- problem constants ----------------
#define B_SZ     2
#define L_SEQ    1024
#define D_MODEL  1024
#define D_INNER  4096
#define N_STATE  16
#define DT_RANK  64
#define M_ROWS   (B_SZ * L_SEQ)          // 2048
#define XDBL_LD  128                     // padded x_dbl leading dim

// ---------------- scratch (device globals; no allocs allowed) ----------------
__device__ float g_xz   [(long)M_ROWS * 2 * D_INNER]; // 2048 x 8192  (xc | res)
__device__ float g_u    [(long)M_ROWS * D_INNER];     // 2048 x 4096 (fp32 for scan)
__device__ float g_xdbl [(long)M_ROWS * XDBL_LD];     // 2048 x 128 (cols 96..127 pad)
__device__ float g_delta[(long)M_ROWS * D_INNER];     // 2048 x 4096
// split activation A' (max: 2048 x 12288)
__device__ __nv_bfloat16 g_ap[(long)M_ROWS * 3 * D_INNER];
// split+transposed weights W' (max: 8192 x 3072)
__device__ __nv_bfloat16 g_wp[(long)(2 * D_INNER) * 3 * D_MODEL];

// ---------------- helpers ----------------
__device__ __forceinline__ float siluf(float x) { return x / (1.0f + __expf(-x)); }
__device__ __forceinline__ float softplusf(float x) {
    return (x > 0.0f) ? (x + log1pf(expf(-x))) : log1pf(expf(x));
}
__device__ __forceinline__ unsigned smem_u32(const void* p) {
    unsigned a;
    asm("{ .reg .u64 t; cvta.to.shared.u64 t, %1; cvt.u32.u64 %0, t; }" : "=r"(a) : "l"(p));
    return a;
}
#define SWZ128(o) ((o) ^ (((o) >> 3) & 0x70))

__device__ __forceinline__ void ldsm4(unsigned* r, unsigned addr) {
    asm volatile("ldmatrix.sync.aligned.m8n8.x4.shared.b16 {%0,%1,%2,%3}, [%4];"
                 : "=r"(r[0]), "=r"(r[1]), "=r"(r[2]), "=r"(r[3]) : "r"(addr));
}
__device__ __forceinline__ void mma16816(float* c, const unsigned* a, const unsigned* b) {
    asm volatile("mma.sync.aligned.m16n8k16.row.col.f32.bf16.bf16.f32 "
                 "{%0,%1,%2,%3}, {%4,%5,%6,%7}, {%8,%9}, {%0,%1,%2,%3};"
                 : "+f"(c[0]), "+f"(c[1]), "+f"(c[2]), "+f"(c[3])
                 : "r"(a[0]), "r"(a[1]), "r"(a[2]), "r"(a[3]), "r"(b[0]), "r"(b[1]));
}
#define CP_ASYNC16(dst, src) \
    asm volatile("cp.async.cg.shared.global [%0], [%1], 16;" :: "r"(dst), "l"(src) : "memory")
#define CP_COMMIT() asm volatile("cp.async.commit_group;" ::: "memory")
#define CP_WAIT(n)  asm volatile("cp.async.wait_group %0;" :: "n"(n) : "memory")

__device__ __forceinline__ void split_store(__nv_bfloat16* base, long o, long K, float v) {
    __nv_bfloat16 hb = __float2bfloat16(v);
    float h = __bfloat162float(hb);
    __nv_bfloat16 lb = __float2bfloat16(v - h);
    base[o]         = hb;
    base[o + K]     = lb;
    base[o + 2 * K] = hb;
}

// ---------------- split prep kernels ----------------
// A'[m, 0:K]=Ah, A'[m, K:2K]=Al, A'[m, 2K:3K]=Ah
__global__ __launch_bounds__(256)
void prep_act(const float* __restrict__ A, int lda, int K,
              __nv_bfloat16* __restrict__ Ap)
{
    long idx = (long)blockIdx.x * 256 + threadIdx.x;
    long m = idx / K;
    int  k = (int)(idx % K);
    split_store(Ap, m * (3L * K) + k, K, A[m * lda + k]);
}

// W[K,N] -> W'[N,3K]: seg0=Wh, seg1=Wh, seg2=Wl (transposed via smem tile)
__global__ __launch_bounds__(256)
void prep_w(const float* __restrict__ W, int N, int K,
            __nv_bfloat16* __restrict__ Wp)
{
    __shared__ float th[32][33];
    __shared__ float tl[32][33];
    int bk = blockIdx.x * 32, bn = blockIdx.y * 32;
    int tx = threadIdx.x & 31, ty = threadIdx.x >> 5;  // (32, 8)
#pragma unroll
    for (int j = 0; j < 4; j++) {
        int k = bk + ty + j * 8;
        float w = W[(long)k * N + bn + tx];
        float h = __bfloat162float(__float2bfloat16(w));
        th[ty + j * 8][tx] = h;
        tl[ty + j * 8][tx] = w - h;
    }
    __syncthreads();
#pragma unroll
    for (int j = 0; j < 4; j++) {
        int n = bn + ty + j * 8;
        long o = (long)n * (3L * K);
        __nv_bfloat16 hb = __float2bfloat16(th[tx][ty + j * 8]);
        __nv_bfloat16 lb = __float2bfloat16(tl[tx][ty + j * 8]);
        Wp[o + bk + tx]         = hb;
        Wp[o + K + bk + tx]     = hb;
        Wp[o + 2 * K + bk + tx] = lb;
    }
}

// zero rows 96..127 of Wx' (N padded to 128, K'=12288)
__global__ __launch_bounds__(256)
void zero_wp_pad(__nv_bfloat16* __restrict__ Wp)
{
    long i = (long)blockIdx.x * 256 + threadIdx.x;
    Wp[96L * 12288 + i] = __float2bfloat16(0.0f);
}

// ---------------- warp-MMA bf16 GEMM: C[M,N] = A'[M,K'] @ W'[N,K']^T -------
// 128x128 CTA tile, BK=64 bf16 (128B rows, SW128), cp.async double-buffered,
// 8 warps each computing a 32x64 warp tile with mma.sync.m16n8k16.
// EPI: 0 = none, 1 = softplus.
#define GSMEM_TOTAL 65536
#define OFF_A0 0u
#define OFF_A1 16384u
#define OFF_B0 32768u
#define OFF_B1 49152u

template<int EPI>
__global__ __launch_bounds__(256)
void gemm_mma(const __nv_bfloat16* __restrict__ Ap, int lda,
              const __nv_bfloat16* __restrict__ Bp, int ldb,
              float* __restrict__ C, int ldc, int T)
{
    extern __shared__ __align__(1024) char smem[];
    const unsigned sb = smem_u32(smem);
    const int tid  = threadIdx.x;
    const int lane = tid & 31;
    const int wid  = tid >> 5;
    const int wm   = (wid & 3) * 32;   // warp row offset in CTA tile
    const int wn   = (wid >> 2) * 64;  // warp col offset
    const long bm  = (long)blockIdx.y * 128;
    const long bn  = (long)blockIdx.x * 128;

    const int ldr  = tid >> 3;         // 0..31 (+32*i -> rows 0..127)
    const int ldc8 = (tid & 7) * 8;    // element col (16B chunks)
    const unsigned swbase = SWZ128((unsigned)(ldr * 128 + ldc8 * 2));

    float acc[2][8][4];
#pragma unroll
    for (int i = 0; i < 2; i++)
#pragma unroll
        for (int j = 0; j < 8; j++)
#pragma unroll
            for (int r = 0; r < 4; r++) acc[i][j][r] = 0.0f;

    const unsigned offA[2] = {OFF_A0, OFF_A1};
    const unsigned offB[2] = {OFF_B0, OFF_B1};

    // issue cp.async for tile t into buffer buf
    auto load_tile = [&](int t, int buf) {
        const __nv_bfloat16* Ab = Ap + bm * lda + (long)t * 64;
        const __nv_bfloat16* Bb = Bp + bn * ldb + (long)t * 64;
#pragma unroll
        for (int i = 0; i < 4; i++) {
            int r = ldr + 32 * i;
            unsigned sw = (r < 32) ? swbase : SWZ128((unsigned)(r * 128 + ldc8 * 2));
            CP_ASYNC16(sb + offA[buf] + sw, Ab + (long)r * lda + ldc8);
            CP_ASYNC16(sb + offB[buf] + sw, Bb + (long)r * ldb + ldc8);
        }
        CP_COMMIT();
    };

    load_tile(0, 0);

    const int lr = lane & 15;         // row within 16-row ldmatrix tile
    const int lh = (lane >> 4) * 16;  // 0 or 16 bytes (k half)

    for (int t = 0; t < T; t++) {
        const int p = t & 1;
        if (t + 1 < T) { load_tile(t + 1, p ^ 1); CP_WAIT(1); }
        else          { CP_WAIT(0); }
        __syncthreads();

        const unsigned sA = sb + offA[p];
        const unsigned sB = sb + offB[p];
#pragma unroll
        for (int ks = 0; ks < 4; ks++) {
            const int kb = ks * 32;  // byte offset of this k16 step
            unsigned af[2][4];
#pragma unroll
            for (int im = 0; im < 2; im++) {
                unsigned addr = sA + SWZ128((unsigned)((wm + im * 16 + lr) * 128 + kb + lh));
                ldsm4(af[im], addr);
            }
            unsigned bf[8][2];
#pragma unroll
            for (int jn = 0; jn < 4; jn++) {
                unsigned q[4];
                unsigned addr = sB + SWZ128((unsigned)((wn + jn * 16 + lr) * 128 + kb + lh));
                ldsm4(q, addr);
                bf[2 * jn][0]     = q[0];
                bf[2 * jn][1]     = q[2];
                bf[2 * jn + 1][0] = q[1];
                bf[2 * jn + 1][1] = q[3];
            }
#pragma unroll
            for (int im = 0; im < 2; im++)
#pragma unroll
                for (int j = 0; j < 8; j++)
                    mma16816(acc[im][j], af[im], bf[j]);
        }
        __syncthreads();   // all warps done with buf p before it is refilled
    }

    // ---- epilogue ----
    const int gid = lane >> 2;
    const int tig = lane & 3;
#pragma unroll
    for (int im = 0; im < 2; im++) {
        long m0 = bm + wm + im * 16 + gid;
#pragma unroll
        for (int j = 0; j < 8; j++) {
            long n0 = bn + wn + j * 8 + 2 * tig;
            float c0 = acc[im][j][0], c1 = acc[im][j][1];
            float c2 = acc[im][j][2], c3 = acc[im][j][3];
            if (EPI == 1) {
                c0 = softplusf(c0); c1 = softplusf(c1);
                c2 = softplusf(c2); c3 = softplusf(c3);
            }
            *reinterpret_cast<float2*>(C + m0 * ldc + n0)       = make_float2(c0, c1);
            *reinterpret_cast<float2*>(C + (m0 + 8) * ldc + n0) = make_float2(c2, c3);
        }
    }
}

// ---------------- depthwise causal conv(4) + bias + SiLU + u-split ---------
__global__ __launch_bounds__(256)
void conv_silu_kernel(const float* __restrict__ Wconv,
                      const float* __restrict__ bconv)
{
    int idx = blockIdx.x * 256 + threadIdx.x;
    int d = idx & (D_INNER - 1);
    int t = (idx >> 12) & (L_SEQ - 1);
    int b = idx >> 22;

    float w0 = Wconv[d * 4 + 0], w1 = Wconv[d * 4 + 1];
    float w2 = Wconv[d * 4 + 2], w3 = Wconv[d * 4 + 3];

    long rowbase = (long)(b * L_SEQ) * (2 * D_INNER);
    float acc = bconv[d];
    if (t - 3 >= 0) acc = fmaf(g_xz[rowbase + (long)(t - 3) * (2 * D_INNER) + d], w0, acc);
    if (t - 2 >= 0) acc = fmaf(g_xz[rowbase + (long)(t - 2) * (2 * D_INNER) + d], w1, acc);
    if (t - 1 >= 0) acc = fmaf(g_xz[rowbase + (long)(t - 1) * (2 * D_INNER) + d], w2, acc);
    acc = fmaf(g_xz[rowbase + (long)t * (2 * D_INNER) + d], w3, acc);

    long m = (long)(b * L_SEQ + t);
    float uu = siluf(acc);
    g_u[m * D_INNER + d] = uu;
    split_store(g_ap, m * (3L * D_INNER) + d, D_INNER, uu);   // u' for x_dbl gemm
}

// ---------------- selective scan + epilogue + y-split ----------------------
__global__ __launch_bounds__(128)
void scan_kernel(const float* __restrict__ A_log,
                 const float* __restrict__ Dp)
{
    extern __shared__ __align__(16) float sBC[];   // [L_SEQ][32]
    const int b = blockIdx.x >> 5;
    const int d = ((blockIdx.x & 31) << 7) + threadIdx.x;
    const long base = (long)b * L_SEQ;

    for (int i = threadIdx.x * 4; i < L_SEQ * 32; i += 128 * 4) {
        int t = i >> 5, c = i & 31;
        *reinterpret_cast<float4*>(&sBC[i]) =
            *reinterpret_cast<const float4*>(&g_xdbl[(base + t) * XDBL_LD + DT_RANK + c]);
    }
    __syncthreads();

    float A[N_STATE];
#pragma unroll
    for (int n = 0; n < N_STATE; n++)
        A[n] = -__expf(A_log[d * N_STATE + n]);
    const float A1 = A[0];
    bool fast = true;
#pragma unroll
    for (int n = 1; n < N_STATE; n++)
        fast = fast && (fabsf(A[n] - (float)(n + 1) * A1) <= 1e-4f * fabsf(A[n]) + 1e-30f);

    const float Dd = Dp[d];
    float h[N_STATE];
#pragma unroll
    for (int n = 0; n < N_STATE; n++) h[n] = 0.0f;

    float pdt[4], pu[4], pr[4];
#pragma unroll
    for (int q = 0; q < 4; q++) {
        long row = base + q;
        pdt[q] = g_delta[row * D_INNER + d];
        pu[q]  = g_u[row * D_INNER + d];
        pr[q]  = g_xz[row * (2 * D_INNER) + D_INNER + d];
    }

    for (int t0 = 0; t0 < L_SEQ; t0 += 4) {
        float cdt[4], cu[4], cr[4];
#pragma unroll
        for (int q = 0; q < 4; q++) { cdt[q] = pdt[q]; cu[q] = pu[q]; cr[q] = pr[q]; }
        if (t0 + 4 < L_SEQ) {
#pragma unroll
            for (int q = 0; q < 4; q++) {
                long row = base + t0 + 4 + q;
                pdt[q] = g_delta[row * D_INNER + d];
                pu[q]  = g_u[row * D_INNER + d];
                pr[q]  = g_xz[row * (2 * D_INNER) + D_INNER + d];
            }
        }
#pragma unroll
        for (int q = 0; q < 4; q++) {
            const int t = t0 + q;
            const float* BC = &sBC[t * 32];
            const float dt = cdt[q], uu = cu[q], rr = cr[q];
            const float dtu = dt * uu;
            float yv = 0.0f;
            if (fast) {
                const float p = __expf(dt * A1);
                float da = p;
#pragma unroll
                for (int n = 0; n < N_STATE; n++) {
                    h[n] = fmaf(da, h[n], dtu * BC[n]);
                    yv = fmaf(h[n], BC[N_STATE + n], yv);
                    da *= p;
                }
            } else {
#pragma unroll
                for (int n = 0; n < N_STATE; n++) {
                    float da = __expf(dt * A[n]);
                    h[n] = fmaf(da, h[n], dtu * BC[n]);
                    yv = fmaf(h[n], BC[N_STATE + n], yv);
                }
            }
            float yo = (yv + uu * Dd) * siluf(rr);
            split_store(g_ap, (base + t) * (3L * D_INNER) + d, D_INNER, yo);
        }
    }
}

// ---------------- launcher ----------------
extern "C" void kernel_launch(void* const* d_in, const int* in_sizes, int n_in,
                              void* d_out, int out_size)
{
    (void)in_sizes; (void)n_in; (void)out_size;
    const float* x     = (const float*)d_in[0];
    const float* Win   = (const float*)d_in[1];
    const float* Wconv = (const float*)d_in[2];
    const float* bconv = (const float*)d_in[3];
    const float* Wx    = (const float*)d_in[4];
    const float* Wdt   = (const float*)d_in[5];
    const float* A_log = (const float*)d_in[6];
    const float* D     = (const float*)d_in[7];
    const float* Wout  = (const float*)d_in[8];
    float* out = (float*)d_out;

    float *xz, *xdbl, *delta;
    __nv_bfloat16 *ap, *wp;
    cudaGetSymbolAddress((void**)&xz,    g_xz);
    cudaGetSymbolAddress((void**)&xdbl,  g_xdbl);
    cudaGetSymbolAddress((void**)&delta, g_delta);
    cudaGetSymbolAddress((void**)&ap,    g_ap);
    cudaGetSymbolAddress((void**)&wp,    g_wp);

    cudaFuncSetAttribute(gemm_mma<0>, cudaFuncAttributeMaxDynamicSharedMemorySize, GSMEM_TOTAL);
    cudaFuncSetAttribute(gemm_mma<1>, cudaFuncAttributeMaxDynamicSharedMemorySize, GSMEM_TOTAL);
    const int scan_smem = L_SEQ * 32 * sizeof(float);
    cudaFuncSetAttribute(scan_kernel, cudaFuncAttributeMaxDynamicSharedMemorySize, scan_smem);

    // ---- GEMM1: xz = x @ Win   (2048 x 8192, K'=3072) ----
    prep_w<<<dim3(D_MODEL / 32, 2 * D_INNER / 32), 256>>>(Win, 2 * D_INNER, D_MODEL, wp);
    prep_act<<<(M_ROWS * D_MODEL) / 256, 256>>>(x, D_MODEL, D_MODEL, ap);
    gemm_mma<0><<<dim3(2 * D_INNER / 128, M_ROWS / 128), 256, GSMEM_TOTAL>>>(
        ap, 3 * D_MODEL, wp, 3 * D_MODEL, xz, 2 * D_INNER, 3 * D_MODEL / 64);

    // ---- conv + SiLU -> u (fp32) + u' (split, into ap) ----
    conv_silu_kernel<<<(B_SZ * L_SEQ * D_INNER) / 256, 256>>>(Wconv, bconv);

    // ---- x_dbl = u @ Wx   (2048 x 128pad, K'=12288) ----
    prep_w<<<dim3(D_INNER / 32, 96 / 32), 256>>>(Wx, 96, D_INNER, wp);
    zero_wp_pad<<<(32 * 12288) / 256, 256>>>(wp);
    gemm_mma<0><<<dim3(1, M_ROWS / 128), 256, GSMEM_TOTAL>>>(
        ap, 3 * D_INNER, wp, 3 * D_INNER, xdbl, XDBL_LD, 3 * D_INNER / 64);

    // ---- delta = softplus(x_dbl[:, :64] @ Wdt)  (2048 x 4096, K'=192) ----
    prep_w<<<dim3(DT_RANK / 32, D_INNER / 32), 256>>>(Wdt, D_INNER, DT_RANK, wp);
    prep_act<<<(M_ROWS * DT_RANK) / 256, 256>>>(xdbl, XDBL_LD, DT_RANK, ap);
    gemm_mma<1><<<dim3(D_INNER / 128, M_ROWS / 128), 256, GSMEM_TOTAL>>>(
        ap, 3 * DT_RANK, wp, 3 * DT_RANK, delta, D_INNER, 3 * DT_RANK / 64);

    // ---- selective scan + epilogue -> y' (split, into ap) ----
    prep_w<<<dim3(D_INNER / 32, D_MODEL / 32), 256>>>(Wout, D_MODEL, D_INNER, wp);
    scan_kernel<<<64, 128, scan_smem>>>(A_log, D);

    // ---- out = y @ Wout   (2048 x 1024, K'=12288) ----
    gemm_mma<0><<<dim3(D_MODEL / 128, M_ROWS / 128), 256, GSMEM_TOTAL>>>(
        ap, 3 * D_INNER, wp, 3 * D_INNER, out, D_MODEL, 3 * D_INNER / 64);
}

// round 6
// speedup vs baseline: 2.9410x; 1.1108x over previous
#include <cuda_runtime.h>
#include <cuda_bf16.h>

// ---------------- problem constants ----------------
#define B_SZ     2
#define L_SEQ    1024
#define D_MODEL  1024
#define D_INNER  4096
#define N_STATE  16
#define DT_RANK  64
#define M_ROWS   (B_SZ * L_SEQ)          // 2048
#define XDBL_LD  128                     // padded x_dbl leading dim

// ---------------- scratch (device globals; no allocs allowed) ----------------
__device__ float g_xz   [(long)M_ROWS * 2 * D_INNER]; // 2048 x 8192  (xc | res)
__device__ float g_u    [(long)M_ROWS * D_INNER];     // 2048 x 4096 (fp32 for scan)
__device__ float g_xdbl [(long)M_ROWS * XDBL_LD];     // 2048 x 128 (cols 96..127 pad)
__device__ float g_delta[(long)M_ROWS * D_INNER];     // 2048 x 4096
__device__ float g_partx[8L * M_ROWS * XDBL_LD];      // split-K partials (xdbl)
__device__ float g_party[4L * M_ROWS * D_MODEL];      // split-K partials (out)
// split activation A' (max: 2048 x 12288)
__device__ __nv_bfloat16 g_ap[(long)M_ROWS * 3 * D_INNER];
// split+transposed weights W' (max: 8192 x 3072)
__device__ __nv_bfloat16 g_wp[(long)(2 * D_INNER) * 3 * D_MODEL];

// ---------------- helpers ----------------
__device__ __forceinline__ float siluf(float x) { return x / (1.0f + __expf(-x)); }
__device__ __forceinline__ float softplusf(float x) {
    return (x > 0.0f) ? (x + log1pf(expf(-x))) : log1pf(expf(x));
}
__device__ __forceinline__ unsigned smem_u32(const void* p) {
    unsigned a;
    asm("{ .reg .u64 t; cvta.to.shared.u64 t, %1; cvt.u32.u64 %0, t; }" : "=r"(a) : "l"(p));
    return a;
}
#define SWZ128(o) ((o) ^ (((o) >> 3) & 0x70))

__device__ __forceinline__ void ldsm4(unsigned* r, unsigned addr) {
    asm volatile("ldmatrix.sync.aligned.m8n8.x4.shared.b16 {%0,%1,%2,%3}, [%4];"
                 : "=r"(r[0]), "=r"(r[1]), "=r"(r[2]), "=r"(r[3]) : "r"(addr));
}
__device__ __forceinline__ void mma16816(float* c, const unsigned* a, const unsigned* b) {
    asm volatile("mma.sync.aligned.m16n8k16.row.col.f32.bf16.bf16.f32 "
                 "{%0,%1,%2,%3}, {%4,%5,%6,%7}, {%8,%9}, {%0,%1,%2,%3};"
                 : "+f"(c[0]), "+f"(c[1]), "+f"(c[2]), "+f"(c[3])
                 : "r"(a[0]), "r"(a[1]), "r"(a[2]), "r"(a[3]), "r"(b[0]), "r"(b[1]));
}
#define CP_ASYNC16(dst, src) \
    asm volatile("cp.async.cg.shared.global [%0], [%1], 16;" :: "r"(dst), "l"(src) : "memory")
#define CP_COMMIT() asm volatile("cp.async.commit_group;" ::: "memory")
#define CP_WAIT(n)  asm volatile("cp.async.wait_group %0;" :: "n"(n) : "memory")

__device__ __forceinline__ void split_store(__nv_bfloat16* base, long o, long K, float v) {
    __nv_bfloat16 hb = __float2bfloat16(v);
    float h = __bfloat162float(hb);
    __nv_bfloat16 lb = __float2bfloat16(v - h);
    base[o]         = hb;
    base[o + K]     = lb;
    base[o + 2 * K] = hb;
}

// ---------------- split prep kernels ----------------
__global__ __launch_bounds__(256)
void prep_act(const float* __restrict__ A, int lda, int K,
              __nv_bfloat16* __restrict__ Ap)
{
    long idx = (long)blockIdx.x * 256 + threadIdx.x;
    long m = idx / K;
    int  k = (int)(idx % K);
    split_store(Ap, m * (3L * K) + k, K, A[m * lda + k]);
}

// W[K,N] -> W'[N,3K]: seg0=Wh, seg1=Wh, seg2=Wl (transposed via smem tile)
__global__ __launch_bounds__(256)
void prep_w(const float* __restrict__ W, int N, int K,
            __nv_bfloat16* __restrict__ Wp)
{
    __shared__ float th[32][33];
    __shared__ float tl[32][33];
    int bk = blockIdx.x * 32, bn = blockIdx.y * 32;
    int tx = threadIdx.x & 31, ty = threadIdx.x >> 5;  // (32, 8)
#pragma unroll
    for (int j = 0; j < 4; j++) {
        int k = bk + ty + j * 8;
        float w = W[(long)k * N + bn + tx];
        float h = __bfloat162float(__float2bfloat16(w));
        th[ty + j * 8][tx] = h;
        tl[ty + j * 8][tx] = w - h;
    }
    __syncthreads();
#pragma unroll
    for (int j = 0; j < 4; j++) {
        int n = bn + ty + j * 8;
        long o = (long)n * (3L * K);
        __nv_bfloat16 hb = __float2bfloat16(th[tx][ty + j * 8]);
        __nv_bfloat16 lb = __float2bfloat16(tl[tx][ty + j * 8]);
        Wp[o + bk + tx]         = hb;
        Wp[o + K + bk + tx]     = hb;
        Wp[o + 2 * K + bk + tx] = lb;
    }
}

// zero rows 96..127 of Wx' (N padded to 128, K'=12288)
__global__ __launch_bounds__(256)
void zero_wp_pad(__nv_bfloat16* __restrict__ Wp)
{
    long i = (long)blockIdx.x * 256 + threadIdx.x;
    Wp[96L * 12288 + i] = __float2bfloat16(0.0f);
}

// deterministic split-K reduction: dst[i] = sum_p parts[p*n + i]
__global__ __launch_bounds__(256)
void reduce_parts(const float* __restrict__ parts, float* __restrict__ dst,
                  long n, int np)
{
    long i = ((long)blockIdx.x * 256 + threadIdx.x) * 4;
    if (i >= n) return;
    float4 s = *reinterpret_cast<const float4*>(parts + i);
    for (int p = 1; p < np; p++) {
        float4 v = *reinterpret_cast<const float4*>(parts + (long)p * n + i);
        s.x += v.x; s.y += v.y; s.z += v.z; s.w += v.w;
    }
    *reinterpret_cast<float4*>(dst + i) = s;
}

// ---------------- warp-MMA bf16 GEMM: C[M,N] = A'[M,K'] @ W'[N,K']^T -------
// 128x128 CTA tile, BK=64 bf16 (128B rows, SW128), 4-stage cp.async ring,
// ONE __syncthreads per K-tile. blockIdx.z = split-K slice (T tiles each).
// EPI: 0 = none, 1 = softplus.
#define STAGES   4
#define STG      32768u        // per stage: A 16KB + B 16KB
#define GSMEM_TOTAL (STAGES * 32768)

template<int EPI>
__global__ __launch_bounds__(256)
void gemm_mma(const __nv_bfloat16* __restrict__ Ap, int lda,
              const __nv_bfloat16* __restrict__ Bp, int ldb,
              float* __restrict__ C, int ldc, int T, long csplit)
{
    extern __shared__ __align__(1024) char smem[];
    const unsigned sb = smem_u32(smem);
    const int tid  = threadIdx.x;
    const int lane = tid & 31;
    const int wid  = tid >> 5;
    const int wm   = (wid & 3) * 32;   // warp row offset in CTA tile
    const int wn   = (wid >> 2) * 64;  // warp col offset
    const long bm  = (long)blockIdx.y * 128;
    const long bn  = (long)blockIdx.x * 128;

    // split-K slice
    Ap += (long)blockIdx.z * T * 64;
    Bp += (long)blockIdx.z * T * 64;
    C  += (long)blockIdx.z * csplit;

    const int ldr  = tid >> 3;         // 0..31 (+32*i -> rows 0..127)
    const int ldc8 = (tid & 7) * 8;    // element col (16B chunks)

    float acc[2][8][4];
#pragma unroll
    for (int i = 0; i < 2; i++)
#pragma unroll
        for (int j = 0; j < 8; j++)
#pragma unroll
            for (int r = 0; r < 4; r++) acc[i][j][r] = 0.0f;

    auto load_tile = [&](int t, int s) {
        const __nv_bfloat16* Ab = Ap + bm * lda + (long)t * 64;
        const __nv_bfloat16* Bb = Bp + bn * ldb + (long)t * 64;
        unsigned oa = sb + (unsigned)s * STG;
        unsigned ob = oa + 16384u;
#pragma unroll
        for (int i = 0; i < 4; i++) {
            int r = ldr + 32 * i;
            unsigned sw = SWZ128((unsigned)(r * 128 + ldc8 * 2));
            CP_ASYNC16(oa + sw, Ab + (long)r * lda + ldc8);
            CP_ASYNC16(ob + sw, Bb + (long)r * ldb + ldc8);
        }
        CP_COMMIT();
    };

    // prologue: stages 0..S-2
#pragma unroll
    for (int s = 0; s < STAGES - 1; s++) {
        if (s < T) load_tile(s, s);
        else       CP_COMMIT();
    }

    const int lr = lane & 15;         // row within 16-row ldmatrix tile
    const int lh = (lane >> 4) * 16;  // 0 or 16 bytes (k half)

    for (int t = 0; t < T; t++) {
        CP_WAIT(STAGES - 2);          // tile t resident
        __syncthreads();              // everyone done with stage (t-1)%S compute
        {
            int tn = t + STAGES - 1;
            if (tn < T) load_tile(tn, tn & (STAGES - 1));
            else        CP_COMMIT();
        }
        const unsigned sA = sb + (unsigned)(t & (STAGES - 1)) * STG;
        const unsigned sB = sA + 16384u;
#pragma unroll
        for (int ks = 0; ks < 4; ks++) {
            const int kb = ks * 32;
            unsigned af[2][4];
#pragma unroll
            for (int im = 0; im < 2; im++) {
                unsigned addr = sA + SWZ128((unsigned)((wm + im * 16 + lr) * 128 + kb + lh));
                ldsm4(af[im], addr);
            }
            unsigned bf[8][2];
#pragma unroll
            for (int jn = 0; jn < 4; jn++) {
                unsigned q[4];
                unsigned addr = sB + SWZ128((unsigned)((wn + jn * 16 + lr) * 128 + kb + lh));
                ldsm4(q, addr);
                bf[2 * jn][0]     = q[0];
                bf[2 * jn][1]     = q[2];
                bf[2 * jn + 1][0] = q[1];
                bf[2 * jn + 1][1] = q[3];
            }
#pragma unroll
            for (int im = 0; im < 2; im++)
#pragma unroll
                for (int j = 0; j < 8; j++)
                    mma16816(acc[im][j], af[im], bf[j]);
        }
    }

    // ---- epilogue ----
    const int gid = lane >> 2;
    const int tig = lane & 3;
#pragma unroll
    for (int im = 0; im < 2; im++) {
        long m0 = bm + wm + im * 16 + gid;
#pragma unroll
        for (int j = 0; j < 8; j++) {
            long n0 = bn + wn + j * 8 + 2 * tig;
            float c0 = acc[im][j][0], c1 = acc[im][j][1];
            float c2 = acc[im][j][2], c3 = acc[im][j][3];
            if (EPI == 1) {
                c0 = softplusf(c0); c1 = softplusf(c1);
                c2 = softplusf(c2); c3 = softplusf(c3);
            }
            *reinterpret_cast<float2*>(C + m0 * ldc + n0)       = make_float2(c0, c1);
            *reinterpret_cast<float2*>(C + (m0 + 8) * ldc + n0) = make_float2(c2, c3);
        }
    }
}

// ---------------- depthwise causal conv(4) + bias + SiLU + u-split ---------
__global__ __launch_bounds__(256)
void conv_silu_kernel(const float* __restrict__ Wconv,
                      const float* __restrict__ bconv)
{
    int idx = blockIdx.x * 256 + threadIdx.x;
    int d = idx & (D_INNER - 1);
    int t = (idx >> 12) & (L_SEQ - 1);
    int b = idx >> 22;

    float w0 = Wconv[d * 4 + 0], w1 = Wconv[d * 4 + 1];
    float w2 = Wconv[d * 4 + 2], w3 = Wconv[d * 4 + 3];

    long rowbase = (long)(b * L_SEQ) * (2 * D_INNER);
    float acc = bconv[d];
    if (t - 3 >= 0) acc = fmaf(g_xz[rowbase + (long)(t - 3) * (2 * D_INNER) + d], w0, acc);
    if (t - 2 >= 0) acc = fmaf(g_xz[rowbase + (long)(t - 2) * (2 * D_INNER) + d], w1, acc);
    if (t - 1 >= 0) acc = fmaf(g_xz[rowbase + (long)(t - 1) * (2 * D_INNER) + d], w2, acc);
    acc = fmaf(g_xz[rowbase + (long)t * (2 * D_INNER) + d], w3, acc);

    long m = (long)(b * L_SEQ + t);
    float uu = siluf(acc);
    g_u[m * D_INNER + d] = uu;
    split_store(g_ap, m * (3L * D_INNER) + d, D_INNER, uu);   // u' for x_dbl gemm
}

// ---------------- selective scan + epilogue + y-split ----------------------
__global__ __launch_bounds__(128)
void scan_kernel(const float* __restrict__ A_log,
                 const float* __restrict__ Dp)
{
    extern __shared__ __align__(16) float sBC[];   // [L_SEQ][32]
    const int b = blockIdx.x >> 5;
    const int d = ((blockIdx.x & 31) << 7) + threadIdx.x;
    const long base = (long)b * L_SEQ;

    for (int i = threadIdx.x * 4; i < L_SEQ * 32; i += 128 * 4) {
        int t = i >> 5, c = i & 31;
        *reinterpret_cast<float4*>(&sBC[i]) =
            *reinterpret_cast<const float4*>(&g_xdbl[(base + t) * XDBL_LD + DT_RANK + c]);
    }
    __syncthreads();

    float A[N_STATE];
#pragma unroll
    for (int n = 0; n < N_STATE; n++)
        A[n] = -__expf(A_log[d * N_STATE + n]);
    const float A1 = A[0];
    bool fast = true;
#pragma unroll
    for (int n = 1; n < N_STATE; n++)
        fast = fast && (fabsf(A[n] - (float)(n + 1) * A1) <= 1e-4f * fabsf(A[n]) + 1e-30f);

    const float Dd = Dp[d];
    float h[N_STATE];
#pragma unroll
    for (int n = 0; n < N_STATE; n++) h[n] = 0.0f;

    float pdt[4], pu[4], pr[4];
#pragma unroll
    for (int q = 0; q < 4; q++) {
        long row = base + q;
        pdt[q] = g_delta[row * D_INNER + d];
        pu[q]  = g_u[row * D_INNER + d];
        pr[q]  = g_xz[row * (2 * D_INNER) + D_INNER + d];
    }

    for (int t0 = 0; t0 < L_SEQ; t0 += 4) {
        float cdt[4], cu[4], cr[4];
#pragma unroll
        for (int q = 0; q < 4; q++) { cdt[q] = pdt[q]; cu[q] = pu[q]; cr[q] = pr[q]; }
        if (t0 + 4 < L_SEQ) {
#pragma unroll
            for (int q = 0; q < 4; q++) {
                long row = base + t0 + 4 + q;
                pdt[q] = g_delta[row * D_INNER + d];
                pu[q]  = g_u[row * D_INNER + d];
                pr[q]  = g_xz[row * (2 * D_INNER) + D_INNER + d];
            }
        }
#pragma unroll
        for (int q = 0; q < 4; q++) {
            const int t = t0 + q;
            const float* BC = &sBC[t * 32];
            const float dt = cdt[q], uu = cu[q], rr = cr[q];
            const float dtu = dt * uu;
            float yv = 0.0f;
            if (fast) {
                const float p = __expf(dt * A1);
                float da = p;
#pragma unroll
                for (int n = 0; n < N_STATE; n++) {
                    h[n] = fmaf(da, h[n], dtu * BC[n]);
                    yv = fmaf(h[n], BC[N_STATE + n], yv);
                    da *= p;
                }
            } else {
#pragma unroll
                for (int n = 0; n < N_STATE; n++) {
                    float da = __expf(dt * A[n]);
                    h[n] = fmaf(da, h[n], dtu * BC[n]);
                    yv = fmaf(h[n], BC[N_STATE + n], yv);
                }
            }
            float yo = (yv + uu * Dd) * siluf(rr);
            split_store(g_ap, (base + t) * (3L * D_INNER) + d, D_INNER, yo);
        }
    }
}

// ---------------- launcher ----------------
extern "C" void kernel_launch(void* const* d_in, const int* in_sizes, int n_in,
                              void* d_out, int out_size)
{
    (void)in_sizes; (void)n_in; (void)out_size;
    const float* x     = (const float*)d_in[0];
    const float* Win   = (const float*)d_in[1];
    const float* Wconv = (const float*)d_in[2];
    const float* bconv = (const float*)d_in[3];
    const float* Wx    = (const float*)d_in[4];
    const float* Wdt   = (const float*)d_in[5];
    const float* A_log = (const float*)d_in[6];
    const float* D     = (const float*)d_in[7];
    const float* Wout  = (const float*)d_in[8];
    float* out = (float*)d_out;

    float *xz, *xdbl, *delta, *partx, *party;
    __nv_bfloat16 *ap, *wp;
    cudaGetSymbolAddress((void**)&xz,    g_xz);
    cudaGetSymbolAddress((void**)&xdbl,  g_xdbl);
    cudaGetSymbolAddress((void**)&delta, g_delta);
    cudaGetSymbolAddress((void**)&partx, g_partx);
    cudaGetSymbolAddress((void**)&party, g_party);
    cudaGetSymbolAddress((void**)&ap,    g_ap);
    cudaGetSymbolAddress((void**)&wp,    g_wp);

    cudaFuncSetAttribute(gemm_mma<0>, cudaFuncAttributeMaxDynamicSharedMemorySize, GSMEM_TOTAL);
    cudaFuncSetAttribute(gemm_mma<1>, cudaFuncAttributeMaxDynamicSharedMemorySize, GSMEM_TOTAL);
    const int scan_smem = L_SEQ * 32 * sizeof(float);
    cudaFuncSetAttribute(scan_kernel, cudaFuncAttributeMaxDynamicSharedMemorySize, scan_smem);

    // ---- GEMM1: xz = x @ Win   (2048 x 8192, K'=3072, T=48) ----
    prep_w<<<dim3(D_MODEL / 32, 2 * D_INNER / 32), 256>>>(Win, 2 * D_INNER, D_MODEL, wp);
    prep_act<<<(M_ROWS * D_MODEL) / 256, 256>>>(x, D_MODEL, D_MODEL, ap);
    gemm_mma<0><<<dim3(2 * D_INNER / 128, M_ROWS / 128, 1), 256, GSMEM_TOTAL>>>(
        ap, 3 * D_MODEL, wp, 3 * D_MODEL, xz, 2 * D_INNER, 48, 0);

    // ---- conv + SiLU -> u (fp32) + u' (split, into ap) ----
    conv_silu_kernel<<<(B_SZ * L_SEQ * D_INNER) / 256, 256>>>(Wconv, bconv);

    // ---- x_dbl = u @ Wx   (2048 x 128pad, K'=12288; split-K x8, T=24) ----
    prep_w<<<dim3(D_INNER / 32, 96 / 32), 256>>>(Wx, 96, D_INNER, wp);
    zero_wp_pad<<<(32 * 12288) / 256, 256>>>(wp);
    gemm_mma<0><<<dim3(1, M_ROWS / 128, 8), 256, GSMEM_TOTAL>>>(
        ap, 3 * D_INNER, wp, 3 * D_INNER, partx, XDBL_LD, 24, (long)M_ROWS * XDBL_LD);
    reduce_parts<<<(M_ROWS * XDBL_LD) / 1024, 256>>>(partx, xdbl, (long)M_ROWS * XDBL_LD, 8);

    // ---- delta = softplus(x_dbl[:, :64] @ Wdt)  (2048 x 4096, K'=192, T=3) ----
    prep_w<<<dim3(DT_RANK / 32, D_INNER / 32), 256>>>(Wdt, D_INNER, DT_RANK, wp);
    prep_act<<<(M_ROWS * DT_RANK) / 256, 256>>>(xdbl, XDBL_LD, DT_RANK, ap);
    gemm_mma<1><<<dim3(D_INNER / 128, M_ROWS / 128, 1), 256, GSMEM_TOTAL>>>(
        ap, 3 * DT_RANK, wp, 3 * DT_RANK, delta, D_INNER, 3, 0);

    // ---- selective scan + epilogue -> y' (split, into ap) ----
    prep_w<<<dim3(D_INNER / 32, D_MODEL / 32), 256>>>(Wout, D_MODEL, D_INNER, wp);
    scan_kernel<<<64, 128, scan_smem>>>(A_log, D);

    // ---- out = y @ Wout   (2048 x 1024, K'=12288; split-K x4, T=48) ----
    gemm_mma<0><<<dim3(D_MODEL / 128, M_ROWS / 128, 4), 256, GSMEM_TOTAL>>>(
        ap, 3 * D_INNER, wp, 3 * D_INNER, party, D_MODEL, 48, (long)M_ROWS * D_MODEL);
    reduce_parts<<<(M_ROWS * D_MODEL) / 1024, 256>>>(party, out, (long)M_ROWS * D_MODEL, 4);
}